// round 3
// baseline (speedup 1.0000x reference)
#include <cuda_runtime.h>
#include <math.h>
#include <stdint.h>

#define Hdim 300
#define H3   900
#define NB   2048
#define SEG  48
#define NR   (NB*SEG)
#define KT   38          // ceil(300/8)

// ---- scratch (device globals: the sanctioned no-alloc path) ----
__device__ float g_padded[(size_t)SEG*NB*Hdim];     // [l][b][h]
__device__ float g_xp[2][(size_t)SEG*NB*H3];        // [z][l][b][g]
__device__ float g_h[2][2][NB*Hdim];                // [z][pingpong][b][h]
__device__ int   g_counts[NB];
__device__ int   g_offsets[NB];

// ---------------- helpers ----------------
__device__ __forceinline__ float tf32r(float x) {
    uint32_t u;
    asm("cvt.rna.tf32.f32 %0, %1;" : "=r"(u) : "f"(x));
    return __uint_as_float(u);
}

__device__ __forceinline__ void mma8(float d[4], const uint32_t a[4], const uint32_t b[2]) {
    asm volatile(
        "mma.sync.aligned.m16n8k8.row.col.f32.tf32.tf32.f32 "
        "{%0,%1,%2,%3},{%4,%5,%6,%7},{%8,%9},{%0,%1,%2,%3};\n"
        : "+f"(d[0]), "+f"(d[1]), "+f"(d[2]), "+f"(d[3])
        : "r"(a[0]), "r"(a[1]), "r"(a[2]), "r"(a[3]), "r"(b[0]), "r"(b[1]));
}

// ---------------- setup kernels ----------------
__global__ void k_zero_counts() {
    int i = blockIdx.x*blockDim.x + threadIdx.x;
    if (i < NB) g_counts[i] = 0;
}

__global__ void k_count(const int* __restrict__ batch) {
    int i = blockIdx.x*blockDim.x + threadIdx.x;
    if (i < NR) atomicAdd(&g_counts[batch[i]], 1);
}

__global__ void k_scan() {
    __shared__ int s[NB];
    int tid = threadIdx.x;
    s[tid]       = g_counts[tid];
    s[tid+1024]  = g_counts[tid+1024];
    __syncthreads();
    for (int off = 1; off < NB; off <<= 1) {
        int v0 = (tid      >= off) ? s[tid      - off] : 0;
        int v1 = (tid+1024 >= off) ? s[tid+1024 - off] : 0;
        __syncthreads();
        s[tid]      += v0;
        s[tid+1024] += v1;
        __syncthreads();
    }
    g_offsets[tid]      = s[tid]      - g_counts[tid];
    g_offsets[tid+1024] = s[tid+1024] - g_counts[tid+1024];
}

__global__ void k_zero_padded() {
    size_t tot = (size_t)SEG*NB*Hdim;
    for (size_t i = (size_t)blockIdx.x*blockDim.x + threadIdx.x; i < tot;
         i += (size_t)gridDim.x*blockDim.x)
        g_padded[i] = 0.f;
}

__global__ void k_pack(const float* __restrict__ x, const float* __restrict__ bias,
                       const int* __restrict__ batch) {
    int i = blockIdx.x;
    int b = batch[i];
    int pos = i - g_offsets[b];
    const float* xr = x + (size_t)i*Hdim;
    float* dst = g_padded + ((size_t)pos*NB + b)*Hdim;
    for (int j = threadIdx.x; j < Hdim; j += blockDim.x) {
        float v = xr[j] + bias[j];
        dst[j] = v > 0.f ? v : 0.f;
    }
}

__global__ void k_h0(const float* __restrict__ x) {
    int b = blockIdx.x;
    int cnt = g_counts[b], off = g_offsets[b];
    for (int j = threadIdx.x; j < Hdim; j += blockDim.x) {
        float m = -3.402823466e38f;
        for (int r = 0; r < cnt; r++)
            m = fmaxf(m, x[(size_t)(off + r)*Hdim + j]);
        g_h[0][0][b*Hdim + j] = m;
        g_h[1][0][b*Hdim + j] = m;
    }
}

// ---------------- big input-projection GEMM (3xTF32 mma) ----------------
// C[m,g] = sum_k padded[m,k] * w_ih[g,k] + b_ih[g], M=NR, N=900, K=300
// Block tile 128x64, 8 warps (2x4), warp tile 64x16, BK=8, double-buffered.
__global__ __launch_bounds__(256) void k_mma_big(
    const float* __restrict__ W0, const float* __restrict__ W1,
    const float* __restrict__ bi0, const float* __restrict__ bi1)
{
    const int K = Hdim;
    int z = blockIdx.z;
    const float* W    = z ? W1 : W0;
    const float* bias = z ? bi1 : bi0;
    const float* A = g_padded;
    float*       C = g_xp[z];

    __shared__ float Ah[2][128][9], Al[2][128][9];
    __shared__ float Bh[2][64][9],  Bl[2][64][9];

    int tid = threadIdx.x;
    int bm = blockIdx.y*128, bn = blockIdx.x*64;
    int warp = tid>>5, lane = tid&31;
    int wm = warp>>2, wn = warp&3;       // 2 x 4 warps
    int gid = lane>>2, tig = lane&3;

    // loaders
    int lr = tid>>1;                     // A row 0..127
    int lh = (tid&1)*4;                  // k offset
    const float* Arow = A + (size_t)(bm + lr)*K;
    int wr = tid>>1;                     // W row (only tid<128)
    bool wok = (tid < 128) && (bn + wr < H3);
    const float* Wrow = W + (size_t)(wok ? (bn + wr) : 0)*K;

    float4 va, vb;
    auto LOAD = [&](int kt){
        int k0 = kt*8 + lh;
        va = make_float4(0.f,0.f,0.f,0.f);
        if (k0 + 3 < K) va = *(const float4*)(Arow + k0);
        if (tid < 128) {
            vb = make_float4(0.f,0.f,0.f,0.f);
            if (wok && k0 + 3 < K) vb = *(const float4*)(Wrow + k0);
        }
    };
    auto STORE = [&](int buf){
        float v[4] = {va.x, va.y, va.z, va.w};
        #pragma unroll
        for (int i = 0; i < 4; i++) {
            float hi = tf32r(v[i]);
            Ah[buf][lr][lh+i] = hi;
            Al[buf][lr][lh+i] = tf32r(v[i] - hi);
        }
        if (tid < 128) {
            float w[4] = {vb.x, vb.y, vb.z, vb.w};
            #pragma unroll
            for (int i = 0; i < 4; i++) {
                float hi = tf32r(w[i]);
                Bh[buf][wr][lh+i] = hi;
                Bl[buf][wr][lh+i] = tf32r(w[i] - hi);
            }
        }
    };

    float acc[4][2][4];
    #pragma unroll
    for (int i=0;i<4;i++) for (int j=0;j<2;j++) for (int q=0;q<4;q++) acc[i][j][q]=0.f;

    auto COMPUTE = [&](int buf){
        uint32_t bfh[2][2], bfl[2][2];
        #pragma unroll
        for (int j = 0; j < 2; j++) {
            int col = wn*16 + j*8 + gid;
            bfh[j][0] = __float_as_uint(Bh[buf][col][tig]);
            bfh[j][1] = __float_as_uint(Bh[buf][col][tig+4]);
            bfl[j][0] = __float_as_uint(Bl[buf][col][tig]);
            bfl[j][1] = __float_as_uint(Bl[buf][col][tig+4]);
        }
        #pragma unroll
        for (int i = 0; i < 4; i++) {
            int r = wm*64 + i*16 + gid;
            uint32_t ah[4], al[4];
            ah[0]=__float_as_uint(Ah[buf][r][tig]);   ah[1]=__float_as_uint(Ah[buf][r+8][tig]);
            ah[2]=__float_as_uint(Ah[buf][r][tig+4]); ah[3]=__float_as_uint(Ah[buf][r+8][tig+4]);
            al[0]=__float_as_uint(Al[buf][r][tig]);   al[1]=__float_as_uint(Al[buf][r+8][tig]);
            al[2]=__float_as_uint(Al[buf][r][tig+4]); al[3]=__float_as_uint(Al[buf][r+8][tig+4]);
            #pragma unroll
            for (int j = 0; j < 2; j++) {
                mma8(acc[i][j], ah, bfh[j]);
                mma8(acc[i][j], al, bfh[j]);
                mma8(acc[i][j], ah, bfl[j]);
            }
        }
    };

    LOAD(0); STORE(0); __syncthreads();
    for (int kt = 0; kt < KT; kt++) {
        int buf = kt & 1;
        if (kt + 1 < KT) LOAD(kt + 1);
        COMPUTE(buf);
        if (kt + 1 < KT) STORE(buf ^ 1);
        __syncthreads();
    }

    #pragma unroll
    for (int i = 0; i < 4; i++) {
        int row = bm + wm*64 + i*16 + gid;
        #pragma unroll
        for (int j = 0; j < 2; j++) {
            int col = bn + wn*16 + j*8 + 2*tig;
            if (col < H3) {
                float* cr0 = C + (size_t)row*H3;
                float* cr1 = C + (size_t)(row+8)*H3;
                cr0[col]   = acc[i][j][0] + bias[col];
                cr0[col+1] = acc[i][j][1] + bias[col+1];
                cr1[col]   = acc[i][j][2] + bias[col];
                cr1[col+1] = acc[i][j][3] + bias[col+1];
            }
        }
    }
}

// ---------------- fused recurrent step: hp GEMM (3xTF32) + gates ----------------
// Grid: x = 10 gate-chunks (32 cols), y = 16 M-tiles (128 molecules), z = 2 dirs.
// Block computes 128x96 hp tile (cols ordered [r0..31 | z0..31 | n0..31]),
// stages it through smem, then applies the GRU gate update.
#define GEMM_SMEM_BYTES (2*128*9*4*2 + 2*96*9*4*2)   // 32256
#define CS_BYTES        (128*100*4)                  // 51200

__global__ __launch_bounds__(256) void k_step(int s, int par,
    const float* __restrict__ W0, const float* __restrict__ W1,
    const float* __restrict__ bh0, const float* __restrict__ bh1,
    float* __restrict__ out)
{
    const int K = Hdim;
    int z = blockIdx.z;
    const float* W   = z ? W1 : W0;
    const float* bhh = z ? bh1 : bh0;
    const float* A   = g_h[z][par];
    int chunk = blockIdx.x;
    int bm = blockIdx.y*128;

    __shared__ __align__(16) char smem[CS_BYTES];   // CS_BYTES > GEMM_SMEM_BYTES
    float (*Ah)[128][9] = (float(*)[128][9])(smem);
    float (*Al)[128][9] = (float(*)[128][9])(smem + 9216);
    float (*Bh)[96][9]  = (float(*)[96][9]) (smem + 18432);
    float (*Bl)[96][9]  = (float(*)[96][9]) (smem + 25344);
    float (*Cs)[100]    = (float(*)[100])   (smem);
    __shared__ float bsh[96];
    __shared__ int   cntS[128], offS[128];

    int tid = threadIdx.x;
    int warp = tid>>5, lane = tid&31;
    int wm = warp>>2, wn = warp&3;       // 2 x 4 warps -> warp tile 64 x 24
    int gid = lane>>2, tig = lane&3;

    if (tid < 96) {
        int gate = tid>>5, c = chunk*32 + (tid&31);
        bsh[tid] = (c < Hdim) ? bhh[gate*Hdim + c] : 0.f;
    }
    if (tid < 128) {
        int b = bm + tid;
        cntS[tid] = g_counts[b];
        offS[tid] = g_offsets[b];
    }

    // loaders
    int lr = tid>>1;
    int lh = (tid&1)*4;
    const float* Arow = A + (size_t)(bm + lr)*K;
    // weight rows: local n -> w_hh row gate*300 + (chunk*32 + n%32)
    int wn_loc = tid>>1;                  // 0..95 for tid<192
    int wgate = wn_loc>>5;
    int wc = chunk*32 + (wn_loc & 31);
    bool wok = (tid < 192) && (wc < Hdim);
    const float* Wrow = W + (size_t)(wok ? (wgate*Hdim + wc) : 0)*K;

    float4 va, vb;
    auto LOAD = [&](int kt){
        int k0 = kt*8 + lh;
        va = make_float4(0.f,0.f,0.f,0.f);
        if (k0 + 3 < K) va = *(const float4*)(Arow + k0);
        if (tid < 192) {
            vb = make_float4(0.f,0.f,0.f,0.f);
            if (wok && k0 + 3 < K) vb = *(const float4*)(Wrow + k0);
        }
    };
    auto STORE = [&](int buf){
        float v[4] = {va.x, va.y, va.z, va.w};
        #pragma unroll
        for (int i = 0; i < 4; i++) {
            float hi = tf32r(v[i]);
            Ah[buf][lr][lh+i] = hi;
            Al[buf][lr][lh+i] = tf32r(v[i] - hi);
        }
        if (tid < 192) {
            float w[4] = {vb.x, vb.y, vb.z, vb.w};
            #pragma unroll
            for (int i = 0; i < 4; i++) {
                float hi = tf32r(w[i]);
                Bh[buf][wn_loc][lh+i] = hi;
                Bl[buf][wn_loc][lh+i] = tf32r(w[i] - hi);
            }
        }
    };

    float acc[4][3][4];
    #pragma unroll
    for (int i=0;i<4;i++) for (int j=0;j<3;j++) for (int q=0;q<4;q++) acc[i][j][q]=0.f;

    auto COMPUTE = [&](int buf){
        uint32_t bfh[3][2], bfl[3][2];
        #pragma unroll
        for (int j = 0; j < 3; j++) {
            int col = wn*24 + j*8 + gid;
            bfh[j][0] = __float_as_uint(Bh[buf][col][tig]);
            bfh[j][1] = __float_as_uint(Bh[buf][col][tig+4]);
            bfl[j][0] = __float_as_uint(Bl[buf][col][tig]);
            bfl[j][1] = __float_as_uint(Bl[buf][col][tig+4]);
        }
        #pragma unroll
        for (int i = 0; i < 4; i++) {
            int r = wm*64 + i*16 + gid;
            uint32_t ah[4], al[4];
            ah[0]=__float_as_uint(Ah[buf][r][tig]);   ah[1]=__float_as_uint(Ah[buf][r+8][tig]);
            ah[2]=__float_as_uint(Ah[buf][r][tig+4]); ah[3]=__float_as_uint(Ah[buf][r+8][tig+4]);
            al[0]=__float_as_uint(Al[buf][r][tig]);   al[1]=__float_as_uint(Al[buf][r+8][tig]);
            al[2]=__float_as_uint(Al[buf][r][tig+4]); al[3]=__float_as_uint(Al[buf][r+8][tig+4]);
            #pragma unroll
            for (int j = 0; j < 3; j++) {
                mma8(acc[i][j], ah, bfh[j]);
                mma8(acc[i][j], al, bfh[j]);
                mma8(acc[i][j], ah, bfl[j]);
            }
        }
    };

    __syncthreads();                      // bsh/cnt/off visible; smem reuse safe
    LOAD(0); STORE(0); __syncthreads();
    for (int kt = 0; kt < KT; kt++) {
        int buf = kt & 1;
        if (kt + 1 < KT) LOAD(kt + 1);
        COMPUTE(buf);
        if (kt + 1 < KT) STORE(buf ^ 1);
        __syncthreads();
    }

    // dump fragments to smem (GEMM buffers dead now)
    #pragma unroll
    for (int i = 0; i < 4; i++) {
        int r0 = wm*64 + i*16 + gid;
        #pragma unroll
        for (int j = 0; j < 3; j++) {
            int cL = wn*24 + j*8 + 2*tig;
            Cs[r0][cL]     = acc[i][j][0];
            Cs[r0][cL+1]   = acc[i][j][1];
            Cs[r0+8][cL]   = acc[i][j][2];
            Cs[r0+8][cL+1] = acc[i][j][3];
        }
    }
    __syncthreads();

    // gate epilogue
    int t = z ? (SEG - 1 - s) : s;
    for (int e = tid; e < 128*32; e += 256) {
        int m = e >> 5, cl = e & 31;
        int c = chunk*32 + cl;
        if (c >= Hdim) continue;
        int b = bm + m;
        const float* xp = g_xp[z] + ((size_t)t*NB + b)*H3;
        float hp_r = Cs[m][cl]      + bsh[cl];
        float hp_z = Cs[m][32 + cl] + bsh[32 + cl];
        float hp_n = Cs[m][64 + cl] + bsh[64 + cl];
        float h_old = g_h[z][par][b*Hdim + c];
        float r  = 1.f/(1.f + expf(-(xp[c]        + hp_r)));
        float zg = 1.f/(1.f + expf(-(xp[Hdim + c] + hp_z)));
        float nn = tanhf(xp[2*Hdim + c] + r*hp_n);
        float hn = (1.f - zg)*nn + zg*h_old;
        g_h[z][par^1][b*Hdim + c] = hn;
        if (t < cntS[m])
            out[(size_t)(offS[m] + t)*(2*Hdim) + z*Hdim + c] = hn;
    }
}

// ---------------- launch ----------------
extern "C" void kernel_launch(void* const* d_in, const int* in_sizes, int n_in,
                              void* d_out, int out_size) {
    const float* x      = (const float*)d_in[0];
    const int*   batch  = (const int*)  d_in[1];
    const float* bias   = (const float*)d_in[4];
    const float* w_ih_f = (const float*)d_in[5];
    const float* w_hh_f = (const float*)d_in[6];
    const float* b_ih_f = (const float*)d_in[7];
    const float* b_hh_f = (const float*)d_in[8];
    const float* w_ih_b = (const float*)d_in[9];
    const float* w_hh_b = (const float*)d_in[10];
    const float* b_ih_b = (const float*)d_in[11];
    const float* b_hh_b = (const float*)d_in[12];
    float* out = (float*)d_out;

    k_zero_counts<<<(NB + 255)/256, 256>>>();
    k_count<<<(NR + 255)/256, 256>>>(batch);
    k_scan<<<1, 1024>>>();
    k_zero_padded<<<4096, 256>>>();
    k_pack<<<NR, 128>>>(x, bias, batch);
    k_h0<<<NB, 128>>>(x);

    dim3 gbig((H3 + 63)/64, NR/128, 2);     // 15 x 768 x 2
    k_mma_big<<<gbig, 256>>>(w_ih_f, w_ih_b, b_ih_f, b_ih_b);

    dim3 gstep((Hdim + 31)/32, NB/128, 2);  // 10 x 16 x 2
    for (int s = 0; s < SEG; s++)
        k_step<<<gstep, 256>>>(s, s & 1, w_hh_f, w_hh_b, b_hh_f, b_hh_b, out);
}